// round 1
// baseline (speedup 1.0000x reference)
#include <cuda_runtime.h>

// OuterProduct_45191645888851 — fused MLP + quadratic form.
// Key identity: value[b] = -( x[b] · MLP(x[b]) )^2  (since A = z z^T).
//
// Inputs (metadata order): x[65536,64], W1[512,64], b1[512], W2[512,512], b2[512],
//                          W3[256,512], b3[256], W4[64,256], b4[64]
// Output: float[65536]

#define TB        32     // batch rows per block
#define NTHREADS  256
#define XSTRIDE   68     // padded row stride for the x tile (16B aligned, avoids worst bank conflicts)

// Dynamic smem layout: sA[TB*512] | sB[TB*512] | xs[TB*XSTRIDE]
static __host__ __device__ constexpr int SMEM_FLOATS = TB * 512 * 2 + TB * XSTRIDE;

template<int K, int N, int INSTRIDE, bool ELU>
__device__ __forceinline__ void layer(const float* __restrict__ sIn,
                                      float* __restrict__ sOut,
                                      const float* __restrict__ W,
                                      const float* __restrict__ b,
                                      int tid)
{
    constexpr int CPT = N / 64;            // columns per thread
    const int c  = tid & 63;               // column group 0..63
    const int r0 = (tid >> 6) * 8;         // first of 8 rows handled by this thread

    float acc[8][CPT];
#pragma unroll
    for (int j = 0; j < CPT; j++) {
        float bv = b[c + j * 64];
#pragma unroll
        for (int i = 0; i < 8; i++) acc[i][j] = bv;
    }

#pragma unroll 2
    for (int k = 0; k < K; k += 4) {
        float4 a[8];
#pragma unroll
        for (int i = 0; i < 8; i++)
            a[i] = *reinterpret_cast<const float4*>(&sIn[(r0 + i) * INSTRIDE + k]);

        float4 w[CPT];
#pragma unroll
        for (int j = 0; j < CPT; j++)
            w[j] = *reinterpret_cast<const float4*>(&W[(c + j * 64) * K + k]);

#pragma unroll
        for (int i = 0; i < 8; i++) {
#pragma unroll
            for (int j = 0; j < CPT; j++) {
                acc[i][j] = fmaf(a[i].x, w[j].x, acc[i][j]);
                acc[i][j] = fmaf(a[i].y, w[j].y, acc[i][j]);
                acc[i][j] = fmaf(a[i].z, w[j].z, acc[i][j]);
                acc[i][j] = fmaf(a[i].w, w[j].w, acc[i][j]);
            }
        }
    }

#pragma unroll
    for (int i = 0; i < 8; i++) {
#pragma unroll
        for (int j = 0; j < CPT; j++) {
            float v = acc[i][j];
            if (ELU) v = (v > 0.0f) ? v : (__expf(v) - 1.0f);
            // consecutive threads (c) write consecutive floats -> conflict-free
            sOut[(r0 + i) * N + c + j * 64] = v;
        }
    }
}

__global__ void __launch_bounds__(NTHREADS, 1)
mlp_quadform_kernel(const float* __restrict__ x,
                    const float* __restrict__ W1, const float* __restrict__ b1,
                    const float* __restrict__ W2, const float* __restrict__ b2,
                    const float* __restrict__ W3, const float* __restrict__ b3,
                    const float* __restrict__ W4, const float* __restrict__ b4,
                    float* __restrict__ out)
{
    extern __shared__ float smem[];
    float* sA = smem;                   // [TB][512]
    float* sB = sA + TB * 512;          // [TB][512]
    float* xs = sB + TB * 512;          // [TB][XSTRIDE]

    const int tid = threadIdx.x;
    const long base = (long)blockIdx.x * TB;

    // Load x tile (coalesced)
#pragma unroll
    for (int idx = tid; idx < TB * 64; idx += NTHREADS) {
        int r = idx >> 6, col = idx & 63;
        xs[r * XSTRIDE + col] = x[(base + r) * 64 + col];
    }
    __syncthreads();

    layer<64,  512, XSTRIDE, true >(xs, sA, W1, b1, tid);   // L1: 64 -> 512, ELU
    __syncthreads();
    layer<512, 512, 512,     true >(sA, sB, W2, b2, tid);   // L2: 512 -> 512, ELU
    __syncthreads();
    layer<512, 256, 512,     true >(sB, sA, W3, b3, tid);   // L3: 512 -> 256, ELU
    __syncthreads();
    layer<256, 64,  256,     false>(sA, sB, W4, b4, tid);   // L4: 256 -> 64, linear
    __syncthreads();

    // value[b] = -(x . z)^2
    if (tid < TB) {
        float s = 0.0f;
#pragma unroll
        for (int k = 0; k < 64; k++)
            s += xs[tid * XSTRIDE + k] * sB[tid * 64 + k];
        out[base + tid] = -s * s;
    }
}

extern "C" void kernel_launch(void* const* d_in, const int* in_sizes, int n_in,
                              void* d_out, int out_size)
{
    const float* x  = (const float*)d_in[0];
    const float* W1 = (const float*)d_in[1];
    const float* b1 = (const float*)d_in[2];
    const float* W2 = (const float*)d_in[3];
    const float* b2 = (const float*)d_in[4];
    const float* W3 = (const float*)d_in[5];
    const float* b3 = (const float*)d_in[6];
    const float* W4 = (const float*)d_in[7];
    const float* b4 = (const float*)d_in[8];
    float* out = (float*)d_out;

    const int batch = in_sizes[0] / 64;          // 65536
    const size_t shmem = SMEM_FLOATS * sizeof(float);   // ~139.8 KB

    cudaFuncSetAttribute(mlp_quadform_kernel,
                         cudaFuncAttributeMaxDynamicSharedMemorySize, (int)shmem);

    dim3 grid(batch / TB);
    mlp_quadform_kernel<<<grid, NTHREADS, shmem>>>(x, W1, b1, W2, b2, W3, b3, W4, b4, out);
}